// round 6
// baseline (speedup 1.0000x reference)
#include <cuda_runtime.h>

#define NB 2048
#define NK 32
#define ND 256

typedef unsigned long long u64;

// scratch for proj = node_flat @ W  (2048 x 256 fp32 = 2 MB)
__device__ float g_proj[NB * ND];

__device__ __forceinline__ u64 ffma2(u64 a, u64 b, u64 c) {
    u64 d;
    asm("fma.rn.f32x2 %0, %1, %2, %3;" : "=l"(d) : "l"(a), "l"(b), "l"(c));
    return d;
}
__device__ __forceinline__ u64 pack2(float x, float y) {
    u64 r; asm("mov.b64 %0, {%1, %2};" : "=l"(r) : "f"(x), "f"(y)); return r;
}
__device__ __forceinline__ float2 unpack2(u64 v) {
    float2 r; asm("mov.b64 {%0, %1}, %2;" : "=f"(r.x), "=f"(r.y) : "l"(v)); return r;
}

// ---------------------------------------------------------------------------
// Kernel 1: proj = node_flat(2048x256) @ W(256x256)
// 64x64 CTA tile, 256 threads, 4x4 thread tile, f32x2 packed FMA.
// ---------------------------------------------------------------------------
__global__ void __launch_bounds__(256) proj_kernel(
    const float* __restrict__ node, const float* __restrict__ W)
{
    __shared__ float As2[32 * 68];   // [kk][row], stride 68 floats (16B-aligned rows)
    __shared__ float Bs[32 * 64];    // [kk][col]

    const int tid = threadIdx.x;
    const int tx = tid & 15;
    const int ty = tid >> 4;
    const int row0 = blockIdx.x * 64;
    const int col0 = blockIdx.y * 64;

    u64 acc[4][2];
#pragma unroll
    for (int i = 0; i < 4; i++) { acc[i][0] = 0ull; acc[i][1] = 0ull; }

    for (int kb = 0; kb < 256; kb += 32) {
#pragma unroll
        for (int t = 0; t < 8; t++) {
            int i = tid + t * 256;
            int r = i >> 5, kk = i & 31;
            As2[kk * 68 + r] = node[(row0 + r) * 256 + kb + kk];
        }
#pragma unroll
        for (int t = 0; t < 8; t++) {
            int i = tid + t * 256;
            int kk = i >> 6, c = i & 63;
            Bs[kk * 64 + c] = W[(kb + kk) * 256 + col0 + c];
        }
        __syncthreads();
#pragma unroll
        for (int kk = 0; kk < 32; kk++) {
            ulonglong2 bp = *reinterpret_cast<const ulonglong2*>(&Bs[kk * 64 + tx * 4]);
            float4 av = *reinterpret_cast<const float4*>(&As2[kk * 68 + ty * 4]);
            float a4[4] = {av.x, av.y, av.z, av.w};
#pragma unroll
            for (int i = 0; i < 4; i++) {
                u64 ap = pack2(a4[i], a4[i]);
                acc[i][0] = ffma2(ap, bp.x, acc[i][0]);
                acc[i][1] = ffma2(ap, bp.y, acc[i][1]);
            }
        }
        __syncthreads();
    }
#pragma unroll
    for (int i = 0; i < 4; i++) {
        ulonglong2 v;
        v.x = acc[i][0];
        v.y = acc[i][1];
        *reinterpret_cast<ulonglong2*>(&g_proj[(row0 + ty * 4 + i) * 256 + col0 + tx * 4]) = v;
    }
}

// ---------------------------------------------------------------------------
// Kernel 2: per-batch attention. One CTA per b (2048 CTAs, 256 threads).
//   P = g_proj[(b%64)*32 : +32]   (32x256, streamed in 64-d chunks, L2-hot)
//   N = neigh[b]                  (32x256, resident in smem)
//   S = P @ N^T + bias ; A = softmax(S) ; out = A @ N
// ---------------------------------------------------------------------------
__global__ void __launch_bounds__(256) attn_kernel(
    const float* __restrict__ neigh, const float* __restrict__ bias,
    float* __restrict__ out, float* __restrict__ Aout)
{
    __shared__ float Ns[32 * 260];   // stride 260 floats = 65 float4 (odd -> conflict-free)
    __shared__ float Pc[32 * 68];    // 64-d chunk of P, stride 68 floats
    __shared__ float As[32 * 33];    // S then A
    __shared__ float bs[32];

    const int b = blockIdx.x;
    const int tid = threadIdx.x;
    const float* nb = neigh + (size_t)b * (NK * ND);

    // load N tile (2048 float4s, coalesced)
#pragma unroll
    for (int t = 0; t < 8; t++) {
        int i = tid + t * 256;
        int row = i >> 6;
        int col = (i & 63) << 2;
        *reinterpret_cast<float4*>(&Ns[row * 260 + col]) =
            *reinterpret_cast<const float4*>(&nb[row * 256 + col]);
    }
    if (tid < 32) bs[tid] = bias[tid];

    const int r0 = (b & 63) << 5;             // (b*32) % 2048
    const float* pb = g_proj + (size_t)r0 * 256;

    const int kp = tid >> 4;                  // 0..15
    const int np = tid & 15;                  // 0..15

    // ---- Phase 1: S = P @ N^T ; thread computes (kp,kp+16) x (np,np+16) ----
    u64 acc[2][2][2];
#pragma unroll
    for (int i = 0; i < 2; i++)
#pragma unroll
        for (int j = 0; j < 2; j++) { acc[i][j][0] = 0ull; acc[i][j][1] = 0ull; }

    for (int ch = 0; ch < 4; ch++) {
        const int d0 = ch * 64;
#pragma unroll
        for (int t = 0; t < 2; t++) {
            int i = tid + t * 256;            // 512 float4s
            int row = i >> 4;
            int col = (i & 15) << 2;
            *reinterpret_cast<float4*>(&Pc[row * 68 + col]) =
                *reinterpret_cast<const float4*>(&pb[row * 256 + d0 + col]);
        }
        __syncthreads();
#pragma unroll
        for (int c4 = 0; c4 < 16; c4++) {
            const int c = c4 * 4;
            ulonglong2 a0 = *reinterpret_cast<const ulonglong2*>(&Pc[kp * 68 + c]);
            ulonglong2 a1 = *reinterpret_cast<const ulonglong2*>(&Pc[(kp + 16) * 68 + c]);
            ulonglong2 b0 = *reinterpret_cast<const ulonglong2*>(&Ns[np * 260 + d0 + c]);
            ulonglong2 b1 = *reinterpret_cast<const ulonglong2*>(&Ns[(np + 16) * 260 + d0 + c]);
            acc[0][0][0] = ffma2(a0.x, b0.x, acc[0][0][0]);
            acc[0][0][1] = ffma2(a0.y, b0.y, acc[0][0][1]);
            acc[0][1][0] = ffma2(a0.x, b1.x, acc[0][1][0]);
            acc[0][1][1] = ffma2(a0.y, b1.y, acc[0][1][1]);
            acc[1][0][0] = ffma2(a1.x, b0.x, acc[1][0][0]);
            acc[1][0][1] = ffma2(a1.y, b0.y, acc[1][0][1]);
            acc[1][1][0] = ffma2(a1.x, b1.x, acc[1][1][0]);
            acc[1][1][1] = ffma2(a1.y, b1.y, acc[1][1][1]);
        }
        __syncthreads();
    }

    // reduce packed halves, add bias, write S
#pragma unroll
    for (int ki = 0; ki < 2; ki++)
#pragma unroll
        for (int ni = 0; ni < 2; ni++) {
            float2 lo = unpack2(acc[ki][ni][0]);
            float2 hi = unpack2(acc[ki][ni][1]);
            float s = (lo.x + lo.y) + (hi.x + hi.y);
            int k = kp + ki * 16;
            int n = np + ni * 16;
            As[k * 33 + n] = s + bs[n];
        }
    __syncthreads();

    // ---- Phase 2: row softmax (warp w handles rows 4w..4w+3, lane = n) ----
    const int lane = tid & 31;
    const int w = tid >> 5;
    float* Aoutb = Aout + (size_t)b * (NK * NK);
#pragma unroll
    for (int rr = 0; rr < 4; rr++) {
        int row = w * 4 + rr;
        float s = As[row * 33 + lane];
        float m = s;
#pragma unroll
        for (int o = 16; o > 0; o >>= 1) m = fmaxf(m, __shfl_xor_sync(0xffffffffu, m, o));
        float e = __expf(s - m);
        float sum = e;
#pragma unroll
        for (int o = 16; o > 0; o >>= 1) sum += __shfl_xor_sync(0xffffffffu, sum, o);
        float a = e / sum;
        As[row * 33 + lane] = a;
        Aoutb[row * 32 + lane] = a;
    }
    __syncthreads();

    // ---- Phase 3: out = A @ N ; warp w -> k rows 4w..4w+3, lane -> d {4l, 128+4l} ----
    const int k0 = w * 4;
    const int dA = lane * 4;
    const int dB = 128 + lane * 4;
    u64 o[4][2][2];
#pragma unroll
    for (int i = 0; i < 4; i++)
#pragma unroll
        for (int j = 0; j < 2; j++) { o[i][j][0] = 0ull; o[i][j][1] = 0ull; }

#pragma unroll 4
    for (int n = 0; n < 32; n++) {
        const ulonglong2 vA = *reinterpret_cast<const ulonglong2*>(&Ns[n * 260 + dA]);
        const ulonglong2 vB = *reinterpret_cast<const ulonglong2*>(&Ns[n * 260 + dB]);
#pragma unroll
        for (int i = 0; i < 4; i++) {
            float a = As[(k0 + i) * 33 + n];   // warp-uniform broadcast
            u64 ap = pack2(a, a);
            o[i][0][0] = ffma2(ap, vA.x, o[i][0][0]);
            o[i][0][1] = ffma2(ap, vA.y, o[i][0][1]);
            o[i][1][0] = ffma2(ap, vB.x, o[i][1][0]);
            o[i][1][1] = ffma2(ap, vB.y, o[i][1][1]);
        }
    }

    float* ob = out + (size_t)b * (NK * ND);
#pragma unroll
    for (int i = 0; i < 4; i++) {
        ulonglong2 vA; vA.x = o[i][0][0]; vA.y = o[i][0][1];
        ulonglong2 vB; vB.x = o[i][1][0]; vB.y = o[i][1][1];
        *reinterpret_cast<ulonglong2*>(&ob[(k0 + i) * 256 + dA]) = vA;
        *reinterpret_cast<ulonglong2*>(&ob[(k0 + i) * 256 + dB]) = vB;
    }
}

// ---------------------------------------------------------------------------
// inputs (metadata order): node(B,T,H) f32, neigh(B,K,T,H) f32, W(D,D) f32,
//                          b(K,) f32, [neighbors_number scalar, unused]
// output: concat[ out(B,K,T,H) = 16,777,216 f32 ; A(B,1,K,K) = 2,097,152 f32 ]
// ---------------------------------------------------------------------------
extern "C" void kernel_launch(void* const* d_in, const int* in_sizes, int n_in,
                              void* d_out, int out_size) {
    const float* node  = (const float*)d_in[0];
    const float* neigh = (const float*)d_in[1];
    const float* W     = (const float*)d_in[2];
    const float* bias  = (const float*)d_in[3];
    (void)in_sizes; (void)n_in; (void)out_size;

    float* out  = (float*)d_out;
    float* Aout = out + (size_t)NB * NK * ND;

    dim3 g1(32, 4);
    proj_kernel<<<g1, 256>>>(node, W);
    attn_kernel<<<NB, 256>>>(neigh, bias, out, Aout);
}

// round 7
// speedup vs baseline: 1.0003x; 1.0003x over previous
#include <cuda_runtime.h>

#define NB 2048
#define NK 32
#define ND 256

typedef unsigned long long u64;

// scratch for proj = node_flat @ W  (2048 x 256 fp32 = 2 MB)
__device__ float g_proj[NB * ND];

__device__ __forceinline__ u64 ffma2(u64 a, u64 b, u64 c) {
    u64 d;
    asm("fma.rn.f32x2 %0, %1, %2, %3;" : "=l"(d) : "l"(a), "l"(b), "l"(c));
    return d;
}
__device__ __forceinline__ u64 pack2(float x, float y) {
    u64 r; asm("mov.b64 %0, {%1, %2};" : "=l"(r) : "f"(x), "f"(y)); return r;
}
__device__ __forceinline__ float2 unpack2(u64 v) {
    float2 r; asm("mov.b64 {%0, %1}, %2;" : "=f"(r.x), "=f"(r.y) : "l"(v)); return r;
}

// ---------------------------------------------------------------------------
// Kernel 1: proj = node_flat(2048x256) @ W(256x256)
// 64x64 CTA tile, 256 threads, 4x4 thread tile, f32x2 packed FMA.
// ---------------------------------------------------------------------------
__global__ void __launch_bounds__(256) proj_kernel(
    const float* __restrict__ node, const float* __restrict__ W)
{
    __shared__ float As2[32 * 68];   // [kk][row], stride 68 floats (16B-aligned rows)
    __shared__ float Bs[32 * 64];    // [kk][col]

    const int tid = threadIdx.x;
    const int tx = tid & 15;
    const int ty = tid >> 4;
    const int row0 = blockIdx.x * 64;
    const int col0 = blockIdx.y * 64;

    u64 acc[4][2];
#pragma unroll
    for (int i = 0; i < 4; i++) { acc[i][0] = 0ull; acc[i][1] = 0ull; }

    for (int kb = 0; kb < 256; kb += 32) {
#pragma unroll
        for (int t = 0; t < 8; t++) {
            int i = tid + t * 256;
            int r = i >> 5, kk = i & 31;
            As2[kk * 68 + r] = node[(row0 + r) * 256 + kb + kk];
        }
#pragma unroll
        for (int t = 0; t < 8; t++) {
            int i = tid + t * 256;
            int kk = i >> 6, c = i & 63;
            Bs[kk * 64 + c] = W[(kb + kk) * 256 + col0 + c];
        }
        __syncthreads();
#pragma unroll
        for (int kk = 0; kk < 32; kk++) {
            ulonglong2 bp = *reinterpret_cast<const ulonglong2*>(&Bs[kk * 64 + tx * 4]);
            float4 av = *reinterpret_cast<const float4*>(&As2[kk * 68 + ty * 4]);
            float a4[4] = {av.x, av.y, av.z, av.w};
#pragma unroll
            for (int i = 0; i < 4; i++) {
                u64 ap = pack2(a4[i], a4[i]);
                acc[i][0] = ffma2(ap, bp.x, acc[i][0]);
                acc[i][1] = ffma2(ap, bp.y, acc[i][1]);
            }
        }
        __syncthreads();
    }
#pragma unroll
    for (int i = 0; i < 4; i++) {
        ulonglong2 v;
        v.x = acc[i][0];
        v.y = acc[i][1];
        *reinterpret_cast<ulonglong2*>(&g_proj[(row0 + ty * 4 + i) * 256 + col0 + tx * 4]) = v;
    }
}

// ---------------------------------------------------------------------------
// Kernel 2: per-batch attention. One CTA per b (2048 CTAs, 256 threads).
//   P = g_proj[(b%64)*32 : +32]   (32x256, streamed in 64-d chunks, L2-hot)
//   N = neigh[b]                  (32x256, resident in smem)
//   S = P @ N^T + bias ; A = softmax(S) ; out = A @ N
// ---------------------------------------------------------------------------
__global__ void __launch_bounds__(256) attn_kernel(
    const float* __restrict__ neigh, const float* __restrict__ bias,
    float* __restrict__ out, float* __restrict__ Aout)
{
    __shared__ float Ns[32 * 260];   // stride 260 floats = 65 float4 (odd -> conflict-free)
    __shared__ float Pc[32 * 68];    // 64-d chunk of P, stride 68 floats
    __shared__ float As[32 * 33];    // S then A
    __shared__ float bs[32];

    const int b = blockIdx.x;
    const int tid = threadIdx.x;
    const float* nb = neigh + (size_t)b * (NK * ND);

    // load N tile (2048 float4s, coalesced)
#pragma unroll
    for (int t = 0; t < 8; t++) {
        int i = tid + t * 256;
        int row = i >> 6;
        int col = (i & 63) << 2;
        *reinterpret_cast<float4*>(&Ns[row * 260 + col]) =
            *reinterpret_cast<const float4*>(&nb[row * 256 + col]);
    }
    if (tid < 32) bs[tid] = bias[tid];

    const int r0 = (b & 63) << 5;             // (b*32) % 2048
    const float* pb = g_proj + (size_t)r0 * 256;

    const int kp = tid >> 4;                  // 0..15
    const int np = tid & 15;                  // 0..15

    // ---- Phase 1: S = P @ N^T ; thread computes (kp,kp+16) x (np,np+16) ----
    u64 acc[2][2][2];
#pragma unroll
    for (int i = 0; i < 2; i++)
#pragma unroll
        for (int j = 0; j < 2; j++) { acc[i][j][0] = 0ull; acc[i][j][1] = 0ull; }

    for (int ch = 0; ch < 4; ch++) {
        const int d0 = ch * 64;
#pragma unroll
        for (int t = 0; t < 2; t++) {
            int i = tid + t * 256;            // 512 float4s
            int row = i >> 4;
            int col = (i & 15) << 2;
            *reinterpret_cast<float4*>(&Pc[row * 68 + col]) =
                *reinterpret_cast<const float4*>(&pb[row * 256 + d0 + col]);
        }
        __syncthreads();
#pragma unroll
        for (int c4 = 0; c4 < 16; c4++) {
            const int c = c4 * 4;
            ulonglong2 a0 = *reinterpret_cast<const ulonglong2*>(&Pc[kp * 68 + c]);
            ulonglong2 a1 = *reinterpret_cast<const ulonglong2*>(&Pc[(kp + 16) * 68 + c]);
            ulonglong2 b0 = *reinterpret_cast<const ulonglong2*>(&Ns[np * 260 + d0 + c]);
            ulonglong2 b1 = *reinterpret_cast<const ulonglong2*>(&Ns[(np + 16) * 260 + d0 + c]);
            acc[0][0][0] = ffma2(a0.x, b0.x, acc[0][0][0]);
            acc[0][0][1] = ffma2(a0.y, b0.y, acc[0][0][1]);
            acc[0][1][0] = ffma2(a0.x, b1.x, acc[0][1][0]);
            acc[0][1][1] = ffma2(a0.y, b1.y, acc[0][1][1]);
            acc[1][0][0] = ffma2(a1.x, b0.x, acc[1][0][0]);
            acc[1][0][1] = ffma2(a1.y, b0.y, acc[1][0][1]);
            acc[1][1][0] = ffma2(a1.x, b1.x, acc[1][1][0]);
            acc[1][1][1] = ffma2(a1.y, b1.y, acc[1][1][1]);
        }
        __syncthreads();
    }

    // reduce packed halves, add bias, write S
#pragma unroll
    for (int ki = 0; ki < 2; ki++)
#pragma unroll
        for (int ni = 0; ni < 2; ni++) {
            float2 lo = unpack2(acc[ki][ni][0]);
            float2 hi = unpack2(acc[ki][ni][1]);
            float s = (lo.x + lo.y) + (hi.x + hi.y);
            int k = kp + ki * 16;
            int n = np + ni * 16;
            As[k * 33 + n] = s + bs[n];
        }
    __syncthreads();

    // ---- Phase 2: row softmax (warp w handles rows 4w..4w+3, lane = n) ----
    const int lane = tid & 31;
    const int w = tid >> 5;
    float* Aoutb = Aout + (size_t)b * (NK * NK);
#pragma unroll
    for (int rr = 0; rr < 4; rr++) {
        int row = w * 4 + rr;
        float s = As[row * 33 + lane];
        float m = s;
#pragma unroll
        for (int o = 16; o > 0; o >>= 1) m = fmaxf(m, __shfl_xor_sync(0xffffffffu, m, o));
        float e = __expf(s - m);
        float sum = e;
#pragma unroll
        for (int o = 16; o > 0; o >>= 1) sum += __shfl_xor_sync(0xffffffffu, sum, o);
        float a = e / sum;
        As[row * 33 + lane] = a;
        Aoutb[row * 32 + lane] = a;
    }
    __syncthreads();

    // ---- Phase 3: out = A @ N ; warp w -> k rows 4w..4w+3, lane -> d {4l, 128+4l} ----
    const int k0 = w * 4;
    const int dA = lane * 4;
    const int dB = 128 + lane * 4;
    u64 o[4][2][2];
#pragma unroll
    for (int i = 0; i < 4; i++)
#pragma unroll
        for (int j = 0; j < 2; j++) { o[i][j][0] = 0ull; o[i][j][1] = 0ull; }

#pragma unroll 4
    for (int n = 0; n < 32; n++) {
        const ulonglong2 vA = *reinterpret_cast<const ulonglong2*>(&Ns[n * 260 + dA]);
        const ulonglong2 vB = *reinterpret_cast<const ulonglong2*>(&Ns[n * 260 + dB]);
#pragma unroll
        for (int i = 0; i < 4; i++) {
            float a = As[(k0 + i) * 33 + n];   // warp-uniform broadcast
            u64 ap = pack2(a, a);
            o[i][0][0] = ffma2(ap, vA.x, o[i][0][0]);
            o[i][0][1] = ffma2(ap, vA.y, o[i][0][1]);
            o[i][1][0] = ffma2(ap, vB.x, o[i][1][0]);
            o[i][1][1] = ffma2(ap, vB.y, o[i][1][1]);
        }
    }

    float* ob = out + (size_t)b * (NK * ND);
#pragma unroll
    for (int i = 0; i < 4; i++) {
        ulonglong2 vA; vA.x = o[i][0][0]; vA.y = o[i][0][1];
        ulonglong2 vB; vB.x = o[i][1][0]; vB.y = o[i][1][1];
        *reinterpret_cast<ulonglong2*>(&ob[(k0 + i) * 256 + dA]) = vA;
        *reinterpret_cast<ulonglong2*>(&ob[(k0 + i) * 256 + dB]) = vB;
    }
}

// ---------------------------------------------------------------------------
// inputs (metadata order): node(B,T,H) f32, neigh(B,K,T,H) f32, W(D,D) f32,
//                          b(K,) f32, [neighbors_number scalar, unused]
// output: concat[ out(B,K,T,H) = 16,777,216 f32 ; A(B,1,K,K) = 2,097,152 f32 ]
// ---------------------------------------------------------------------------
extern "C" void kernel_launch(void* const* d_in, const int* in_sizes, int n_in,
                              void* d_out, int out_size) {
    const float* node  = (const float*)d_in[0];
    const float* neigh = (const float*)d_in[1];
    const float* W     = (const float*)d_in[2];
    const float* bias  = (const float*)d_in[3];
    (void)in_sizes; (void)n_in; (void)out_size;

    float* out  = (float*)d_out;
    float* Aout = out + (size_t)NB * NK * ND;

    dim3 g1(32, 4);
    proj_kernel<<<g1, 256>>>(node, W);
    attn_kernel<<<NB, 256>>>(neigh, bias, out, Aout);
}